// round 15
// baseline (speedup 1.0000x reference)
#include <cuda_runtime.h>

typedef unsigned long long u64;

// ---------- f32x2 packed helpers (Blackwell sm_103a) ----------
__device__ __forceinline__ u64 pk2(float lo, float hi) {
    u64 r; asm("mov.b64 %0,{%1,%2};" : "=l"(r) : "f"(lo), "f"(hi)); return r;
}
__device__ __forceinline__ void unpk2(u64 v, float& lo, float& hi) {
    asm("mov.b64 {%0,%1},%2;" : "=f"(lo), "=f"(hi) : "l"(v));
}
__device__ __forceinline__ u64 fma2(u64 a, u64 b, u64 c) {
    u64 d; asm("fma.rn.f32x2 %0,%1,%2,%3;" : "=l"(d) : "l"(a), "l"(b), "l"(c)); return d;
}
__device__ __forceinline__ u64 add2(u64 a, u64 b) {
    u64 d; asm("add.rn.f32x2 %0,%1,%2;" : "=l"(d) : "l"(a), "l"(b)); return d;
}
__device__ __forceinline__ u64 mul2(u64 a, u64 b) {
    u64 d; asm("mul.rn.f32x2 %0,%1,%2;" : "=l"(d) : "l"(a), "l"(b)); return d;
}
__device__ __forceinline__ u64 shfl64(u64 v, int m) {
    return __shfl_xor_sync(0xffffffffu, v, m);
}

// ---------- activations (R7 structure — empirically best) ----------
__device__ __forceinline__ float ex2a(float x) {
    float y; asm("ex2.approx.f32 %0,%1;" : "=f"(y) : "f"(x)); return y;
}
__device__ __forceinline__ float rcpa(float x) {
    float y; asm("rcp.approx.f32 %0,%1;" : "=f"(y) : "f"(x)); return y;
}
#define SSC (-1.4426950408889634f)     /* -log2(e)   : sigmoid pre-scale */
#define TSC (-2.8853900817779268f)     /* -2*log2(e) : tanh pre-scale    */
#define INV_TSC (-0.3465735902799726f) /* 1/TSC                          */

__device__ __forceinline__ float sigS(float s)  { return rcpa(1.0f + ex2a(s)); }
__device__ __forceinline__ float tanhU(float s) { return fmaf(2.0f, rcpa(1.0f + ex2a(s)), -1.0f); }

// TWO batch rows per warp. Row A and row B execute back-to-back in the same
// instruction stream with no intervening barriers, so ptxas interleaves row
// B's LDS/dot into row A's activation-latency bubbles (in-stream ILP replaces
// the failed cross-warp overlap). Weights are shared between rows.
// Per row: lanes 0-19 = layer-1 unit j=lane ((i,f) in aif, (g,o) in ago, dots
// over the h-section); lane 20 = all four layer-2 gates (c-section, weights
// /TSC), h2-recurrent via wh2A/wh2B at chain position 2. cloc TSC-prescaled.
__global__ void __launch_bounds__(128)
lstm_warp_kernel(const float* __restrict__ xin,
                 const float* __restrict__ Wih1, const float* __restrict__ Whh1,
                 const float* __restrict__ bih1, const float* __restrict__ bhh1,
                 const float* __restrict__ Wih2, const float* __restrict__ Whh2,
                 const float* __restrict__ bih2, const float* __restrict__ bhh2,
                 float* __restrict__ out, int B, int T, int F)
{
    const int w    = threadIdx.x >> 5;
    const int lane = threadIdx.x & 31;
    const int gw   = blockIdx.x * 4 + w;       // global warp id (512 total)
    const int b0   = 2 * gw;                   // rows b0, b0+1

    // [warp][row][ping][0:32)=(h,h) dup, [32:64)=(TSC*c,TSC*c) dup
    __shared__ __align__(16) u64 sbuf[4][2][2][64];

    if (b0 + 1 >= B + 1) return;  // (grid sized exactly; keep guard trivial)

    const bool is20 = (lane == 20);
    const int  sec  = (lane < 20) ? 0 : 32;
    u64* const wb0  = &sbuf[w][0][0][0];
    u64* const wb1  = &sbuf[w][1][0][0];

    // ---- per-lane weights (prescaled, SHARED by both rows); default zero ----
    u64 wif[20], wgo[20];
#pragma unroll
    for (int k = 0; k < 20; k++) { wif[k] = 0ull; wgo[k] = 0ull; }
    u64 wxif = 0ull, wxgo = 0ull, bif = 0ull, bgo = 0ull;
    u64 wh2A = 0ull, wh2B = 0ull;

    if (lane < 20) {
        const int j = lane;
#pragma unroll
        for (int k = 0; k < 20; k++) {
            wif[k] = pk2(SSC * Whh1[j * 20 + k],        SSC * Whh1[(20 + j) * 20 + k]);
            wgo[k] = pk2(TSC * Whh1[(40 + j) * 20 + k], SSC * Whh1[(60 + j) * 20 + k]);
        }
        wxif = pk2(SSC * Wih1[j],      SSC * Wih1[20 + j]);
        wxgo = pk2(TSC * Wih1[40 + j], SSC * Wih1[60 + j]);
        bif  = pk2(SSC * (bih1[j] + bhh1[j]),
                   SSC * (bih1[20 + j] + bhh1[20 + j]));
        bgo  = pk2(TSC * (bih1[40 + j] + bhh1[40 + j]),
                   SSC * (bih1[60 + j] + bhh1[60 + j]));
    } else if (lane == 20) {
#pragma unroll
        for (int k = 0; k < 20; k++) {
            wif[k] = pk2(SSC * INV_TSC * Wih2[k],  SSC * INV_TSC * Wih2[20 + k]);
            wgo[k] = pk2(Wih2[40 + k],             SSC * INV_TSC * Wih2[60 + k]);
        }
        bif  = pk2(SSC * (bih2[0] + bhh2[0]), SSC * (bih2[1] + bhh2[1]));
        bgo  = pk2(TSC * (bih2[2] + bhh2[2]), SSC * (bih2[3] + bhh2[3]));
        wh2A = pk2(SSC * Whh2[0], SSC * Whh2[1]);   // h2 joins at chain pos 2
        wh2B = pk2(TSC * Whh2[2], SSC * Whh2[3]);
    }

    // butterfly-path L2 weights (flush / future phase only); input is TSC*c1
    u64 uif = 0ull, ugo = 0ull;
    if (lane < 20) {
        uif = pk2(SSC * INV_TSC * Wih2[lane],  SSC * INV_TSC * Wih2[20 + lane]);
        ugo = pk2(Wih2[40 + lane],             SSC * INV_TSC * Wih2[60 + lane]);
    }
    const u64 wh2if = pk2(SSC * Whh2[0], SSC * Whh2[1]);
    const u64 wh2go = pk2(TSC * Whh2[2], SSC * Whh2[3]);
    const u64 b2if  = pk2(SSC * (bih2[0] + bhh2[0]), SSC * (bih2[1] + bhh2[1]));
    const u64 b2go  = pk2(TSC * (bih2[2] + bhh2[2]), SSC * (bih2[3] + bhh2[3]));

    // ---- per-row state ----
    float c0 = 0.0f, h0 = 0.0f;   // row A: lanes<20 TSC*c1/h1; lane20 TSC*c2/h2
    float c1r = 0.0f, h1r = 0.0f; // row B
    int   p   = 0;
    wb0[lane] = 0ull; wb0[32 + lane] = 0ull;
    wb1[lane] = 0ull; wb1[32 + lane] = 0ull;

    // ---- one fused SIMD step for one row (no syncwarp; R13-validated) ----
    auto step = [&](float x, float& cl, float& hl, u64* base) {
        const ulonglong2* hp = (const ulonglong2*)(base + (p << 6) + sec);
        const ulonglong2 v0 = hp[0], v1 = hp[1], v2 = hp[2], v3 = hp[3], v4 = hp[4];
        const ulonglong2 v5 = hp[5], v6 = hp[6], v7 = hp[7], v8 = hp[8], v9 = hp[9];
        const u64 xx = pk2(x, x);
        const u64 hh = pk2(hl, hl);            // joins at chain position 2
        u64 aA = fma2(wh2A, hh, fma2(wxif, xx, bif));
        u64 gA = fma2(wh2B, hh, fma2(wxgo, xx, bgo));
        u64 aB = mul2(wif[1], v0.y), gB = mul2(wgo[1], v0.y);
        aA = fma2(wif[0],  v0.x, aA); gA = fma2(wgo[0],  v0.x, gA);
        aB = fma2(wif[3],  v1.y, aB); gB = fma2(wgo[3],  v1.y, gB);
        aA = fma2(wif[2],  v1.x, aA); gA = fma2(wgo[2],  v1.x, gA);
        aB = fma2(wif[5],  v2.y, aB); gB = fma2(wgo[5],  v2.y, gB);
        aA = fma2(wif[4],  v2.x, aA); gA = fma2(wgo[4],  v2.x, gA);
        aB = fma2(wif[7],  v3.y, aB); gB = fma2(wgo[7],  v3.y, gB);
        aA = fma2(wif[6],  v3.x, aA); gA = fma2(wgo[6],  v3.x, gA);
        aB = fma2(wif[9],  v4.y, aB); gB = fma2(wgo[9],  v4.y, gB);
        aA = fma2(wif[8],  v4.x, aA); gA = fma2(wgo[8],  v4.x, gA);
        aB = fma2(wif[11], v5.y, aB); gB = fma2(wgo[11], v5.y, gB);
        aA = fma2(wif[10], v5.x, aA); gA = fma2(wgo[10], v5.x, gA);
        aB = fma2(wif[13], v6.y, aB); gB = fma2(wgo[13], v6.y, gB);
        aA = fma2(wif[12], v6.x, aA); gA = fma2(wgo[12], v6.x, gA);
        aB = fma2(wif[15], v7.y, aB); gB = fma2(wgo[15], v7.y, gB);
        aA = fma2(wif[14], v7.x, aA); gA = fma2(wgo[14], v7.x, gA);
        aB = fma2(wif[17], v8.y, aB); gB = fma2(wgo[17], v8.y, gB);
        aA = fma2(wif[16], v8.x, aA); gA = fma2(wgo[16], v8.x, gA);
        aB = fma2(wif[19], v9.y, aB); gB = fma2(wgo[19], v9.y, gB);
        aA = fma2(wif[18], v9.x, aA); gA = fma2(wgo[18], v9.x, gA);
        const u64 aif = add2(aA, aB), ago = add2(gA, gB);

        float is, fs, gs, os; unpk2(aif, is, fs); unpk2(ago, gs, os);
        const float ei = ex2a(is), ef = ex2a(fs), eg = ex2a(gs), eo = ex2a(os);
        const float si  = rcpa(1.0f + ei), sf = rcpa(1.0f + ef);
        const float tgT = fmaf(2.0f * TSC, rcpa(1.0f + eg), -TSC);  // TSC*tanh
        const float so  = rcpa(1.0f + eo);

        cl = fmaf(sf, cl, si * tgT);           // TSC-scaled c update
        u64* sb = base + ((p ^ 1) << 6);
        sb[32 + lane] = pk2(cl, cl);           // c-store early (lane-20 input)
        hl = so * tanhU(cl);
        sb[lane] = pk2(hl, hl);
    };

    // ---- butterfly L2 (flush / future phase); c1v is TSC-scaled ----
    auto step_l2 = [&](float c1v, float& c2s, float& h2s) {
        const u64 cc = pk2(c1v, c1v);
        u64 pif = mul2(uif, cc), pgo = mul2(ugo, cc);
#pragma unroll
        for (int m = 16; m; m >>= 1) {
            pif = add2(pif, shfl64(pif, m));
            pgo = add2(pgo, shfl64(pgo, m));
        }
        const u64 hh = pk2(h2s, h2s);
        pif = fma2(wh2if, hh, add2(pif, b2if));
        pgo = fma2(wh2go, hh, add2(pgo, b2go));
        float i2, f2, g2, o2; unpk2(pif, i2, f2); unpk2(pgo, g2, o2);
        const float s2i = sigS(i2), s2f = sigS(f2), t2g = tanhU(g2), s2o = sigS(o2);
        c2s = fmaf(s2f, c2s, s2i * t2g);
        h2s = s2o * tanhU(c2s * TSC);
    };

    const float* xr0 = xin + (size_t)b0 * T;
    const float* xr1 = xin + (size_t)(b0 + 1) * T;
    float*       or0 = out + (size_t)b0 * (T + F);
    float*       or1 = out + (size_t)(b0 + 1) * (T + F);

    // ---- peel t = 0: L1 only for both rows; reset lane-20 L2 state ----
    float xn0 = __ldg(xr0 + 1);
    float xn1 = __ldg(xr1 + 1);
    step(__ldg(xr0), c0,  h0,  wb0);
    step(__ldg(xr1), c1r, h1r, wb1);
    p ^= 1;
    if (is20) { c0 = 0.0f; h0 = 0.0f; c1r = 0.0f; h1r = 0.0f; }

    // ---- main loop: rows A and B back-to-back, no barriers between ----
#pragma unroll 1
    for (int t = 1; t < T; t++) {
        const float x0 = xn0, x1 = xn1;
        if (t + 1 < T) { xn0 = __ldg(xr0 + t + 1); xn1 = __ldg(xr1 + t + 1); }
        step(x0, c0,  h0,  wb0);
        step(x1, c1r, h1r, wb1);
        p ^= 1;
        if (is20) { or0[t - 1] = c0 * INV_TSC; or1[t - 1] = c1r * INV_TSC; }
    }

    // ---- flush + future, row A ----
    {
        float c2s = __shfl_sync(0xffffffffu, c0, 20) * INV_TSC;
        float h2s = __shfl_sync(0xffffffffu, h0, 20);
        step_l2(c0, c2s, h2s);                 // c0 = TSC*c1(T-1) per lane
        if (lane == 0) or0[T - 1] = c2s;
#pragma unroll 1
        for (int f = 0; f < F; f++) {
            step(c2s, c0, h0, wb0);
            p ^= 1;
            step_l2(c0, c2s, h2s);
            if (lane == 0) or0[T + f] = c2s;
        }
    }
    // ---- flush + future, row B ----
    {
        float c2s = __shfl_sync(0xffffffffu, c1r, 20) * INV_TSC;
        float h2s = __shfl_sync(0xffffffffu, h1r, 20);
        step_l2(c1r, c2s, h2s);
        if (lane == 0) or1[T - 1] = c2s;
#pragma unroll 1
        for (int f = 0; f < F; f++) {
            step(c2s, c1r, h1r, wb1);
            p ^= 1;
            step_l2(c1r, c2s, h2s);
            if (lane == 0) or1[T + f] = c2s;
        }
    }
}

extern "C" void kernel_launch(void* const* d_in, const int* in_sizes, int n_in,
                              void* d_out, int out_size)
{
    const float* xin  = (const float*)d_in[0];
    const float* Wih1 = (const float*)d_in[1];
    const float* Whh1 = (const float*)d_in[2];
    const float* bih1 = (const float*)d_in[3];
    const float* bhh1 = (const float*)d_in[4];
    const float* Wih2 = (const float*)d_in[5];
    const float* Whh2 = (const float*)d_in[6];
    const float* bih2 = (const float*)d_in[7];
    const float* bhh2 = (const float*)d_in[8];

    const int B = 1024;
    const int T = in_sizes[0] / B;          // 4096
    const int F = out_size / B - T;         // 16

    dim3 grid(B / 8), block(128);           // 128 blocks: 2 rows per warp
    lstm_warp_kernel<<<grid, block>>>(xin, Wih1, Whh1, bih1, bhh1,
                                      Wih2, Whh2, bih2, bhh2,
                                      (float*)d_out, B, T, F);
}

// round 16
// speedup vs baseline: 1.2324x; 1.2324x over previous
#include <cuda_runtime.h>

typedef unsigned long long u64;

// ---------- f32x2 packed helpers (Blackwell sm_103a) ----------
__device__ __forceinline__ u64 pk2(float lo, float hi) {
    u64 r; asm("mov.b64 %0,{%1,%2};" : "=l"(r) : "f"(lo), "f"(hi)); return r;
}
__device__ __forceinline__ void unpk2(u64 v, float& lo, float& hi) {
    asm("mov.b64 {%0,%1},%2;" : "=f"(lo), "=f"(hi) : "l"(v));
}
__device__ __forceinline__ u64 fma2(u64 a, u64 b, u64 c) {
    u64 d; asm("fma.rn.f32x2 %0,%1,%2,%3;" : "=l"(d) : "l"(a), "l"(b), "l"(c)); return d;
}
__device__ __forceinline__ u64 add2(u64 a, u64 b) {
    u64 d; asm("add.rn.f32x2 %0,%1,%2;" : "=l"(d) : "l"(a), "l"(b)); return d;
}
__device__ __forceinline__ u64 mul2(u64 a, u64 b) {
    u64 d; asm("mul.rn.f32x2 %0,%1,%2;" : "=l"(d) : "l"(a), "l"(b)); return d;
}
__device__ __forceinline__ u64 shfl64(u64 v, int m) {
    return __shfl_xor_sync(0xffffffffu, v, m);
}

// ---------- activations (R7 structure — empirically best) ----------
__device__ __forceinline__ float ex2a(float x) {
    float y; asm("ex2.approx.f32 %0,%1;" : "=f"(y) : "f"(x)); return y;
}
__device__ __forceinline__ float rcpa(float x) {
    float y; asm("rcp.approx.f32 %0,%1;" : "=f"(y) : "f"(x)); return y;
}
#define SSC (-1.4426950408889634f)     /* -log2(e)   : sigmoid pre-scale */
#define TSC (-2.8853900817779268f)     /* -2*log2(e) : tanh pre-scale    */
#define INV_TSC (-0.3465735902799726f) /* 1/TSC                          */

__device__ __forceinline__ float sigS(float s)  { return rcpa(1.0f + ex2a(s)); }
__device__ __forceinline__ float tanhU(float s) { return fmaf(2.0f, rcpa(1.0f + ex2a(s)), -1.0f); }

// TWO batch rows per warp, FUSED step-pair: all LDS for both rows happen
// BEFORE any STS (R15 failed because row B's loads sat behind row A's stores
// and ptxas won't hoist LDS across STS -> full serialization). With loads
// hoisted, the 8 accumulator chains (4 per row) interleave freely and row B's
// fma2 work fills row A's activation-latency bubbles.
// Per row: lanes 0-19 = layer-1 unit j=lane; lane 20 = all four layer-2 gates
// (c-section dots, weights /TSC, h2-recurrent at chain pos 2). cloc carries
// TSC*c. Weights shared between rows.
__global__ void __launch_bounds__(128)
lstm_warp_kernel(const float* __restrict__ xin,
                 const float* __restrict__ Wih1, const float* __restrict__ Whh1,
                 const float* __restrict__ bih1, const float* __restrict__ bhh1,
                 const float* __restrict__ Wih2, const float* __restrict__ Whh2,
                 const float* __restrict__ bih2, const float* __restrict__ bhh2,
                 float* __restrict__ out, int B, int T, int F)
{
    const int w    = threadIdx.x >> 5;
    const int lane = threadIdx.x & 31;
    const int gw   = blockIdx.x * 4 + w;       // global warp id (512 total)
    const int b0   = 2 * gw;                   // rows b0, b0+1

    // [warp][row][ping][0:32)=(h,h) dup, [32:64)=(TSC*c,TSC*c) dup
    __shared__ __align__(16) u64 sbuf[4][2][2][64];

    const bool is20 = (lane == 20);
    const int  sec  = (lane < 20) ? 0 : 32;
    u64* const wb0  = &sbuf[w][0][0][0];
    u64* const wb1  = &sbuf[w][1][0][0];

    // ---- per-lane weights (prescaled, SHARED by both rows); default zero ----
    u64 wif[20], wgo[20];
#pragma unroll
    for (int k = 0; k < 20; k++) { wif[k] = 0ull; wgo[k] = 0ull; }
    u64 wxif = 0ull, wxgo = 0ull, bif = 0ull, bgo = 0ull;
    u64 wh2A = 0ull, wh2B = 0ull;

    if (lane < 20) {
        const int j = lane;
#pragma unroll
        for (int k = 0; k < 20; k++) {
            wif[k] = pk2(SSC * Whh1[j * 20 + k],        SSC * Whh1[(20 + j) * 20 + k]);
            wgo[k] = pk2(TSC * Whh1[(40 + j) * 20 + k], SSC * Whh1[(60 + j) * 20 + k]);
        }
        wxif = pk2(SSC * Wih1[j],      SSC * Wih1[20 + j]);
        wxgo = pk2(TSC * Wih1[40 + j], SSC * Wih1[60 + j]);
        bif  = pk2(SSC * (bih1[j] + bhh1[j]),
                   SSC * (bih1[20 + j] + bhh1[20 + j]));
        bgo  = pk2(TSC * (bih1[40 + j] + bhh1[40 + j]),
                   SSC * (bih1[60 + j] + bhh1[60 + j]));
    } else if (lane == 20) {
#pragma unroll
        for (int k = 0; k < 20; k++) {
            wif[k] = pk2(SSC * INV_TSC * Wih2[k],  SSC * INV_TSC * Wih2[20 + k]);
            wgo[k] = pk2(Wih2[40 + k],             SSC * INV_TSC * Wih2[60 + k]);
        }
        bif  = pk2(SSC * (bih2[0] + bhh2[0]), SSC * (bih2[1] + bhh2[1]));
        bgo  = pk2(TSC * (bih2[2] + bhh2[2]), SSC * (bih2[3] + bhh2[3]));
        wh2A = pk2(SSC * Whh2[0], SSC * Whh2[1]);   // h2 joins at chain pos 2
        wh2B = pk2(TSC * Whh2[2], SSC * Whh2[3]);
    }

    // butterfly-path L2 weights (flush / future phase only); input is TSC*c1
    u64 uifW = 0ull, ugoW = 0ull;
    if (lane < 20) {
        uifW = pk2(SSC * INV_TSC * Wih2[lane],  SSC * INV_TSC * Wih2[20 + lane]);
        ugoW = pk2(Wih2[40 + lane],             SSC * INV_TSC * Wih2[60 + lane]);
    }
    const u64 wh2if = pk2(SSC * Whh2[0], SSC * Whh2[1]);
    const u64 wh2go = pk2(TSC * Whh2[2], SSC * Whh2[3]);
    const u64 b2if  = pk2(SSC * (bih2[0] + bhh2[0]), SSC * (bih2[1] + bhh2[1]));
    const u64 b2go  = pk2(TSC * (bih2[2] + bhh2[2]), SSC * (bih2[3] + bhh2[3]));

    // ---- per-row state ----
    float cA = 0.0f, hA = 0.0f;   // row A
    float cB = 0.0f, hB = 0.0f;   // row B
    int   p  = 0;
    wb0[lane] = 0ull; wb0[32 + lane] = 0ull;
    wb1[lane] = 0ull; wb1[32 + lane] = 0ull;

    // ---- fused step-pair: all loads first, stores last ----
    auto step2 = [&](float xA, float xB) {
        const ulonglong2* pA = (const ulonglong2*)(wb0 + (p << 6) + sec);
        const ulonglong2* pB = (const ulonglong2*)(wb1 + (p << 6) + sec);
        const u64 xxA = pk2(xA, xA), xxB = pk2(xB, xB);
        const u64 hhA = pk2(hA, hA), hhB = pk2(hB, hB);

        u64 uA = fma2(wh2A, hhA, fma2(wxif, xxA, bif));
        u64 sA = fma2(wh2B, hhA, fma2(wxgo, xxA, bgo));
        u64 uB = fma2(wh2A, hhB, fma2(wxif, xxB, bif));
        u64 sB = fma2(wh2B, hhB, fma2(wxgo, xxB, bgo));
        u64 vA = 0ull, tA = 0ull, vB = 0ull, tB = 0ull;
#pragma unroll
        for (int m = 0; m < 10; m++) {
            const ulonglong2 a = pA[m];        // all LDS precede all STS
            const ulonglong2 b = pB[m];
            uA = fma2(wif[2 * m],     a.x, uA);  sA = fma2(wgo[2 * m],     a.x, sA);
            uB = fma2(wif[2 * m],     b.x, uB);  sB = fma2(wgo[2 * m],     b.x, sB);
            vA = fma2(wif[2 * m + 1], a.y, vA);  tA = fma2(wgo[2 * m + 1], a.y, tA);
            vB = fma2(wif[2 * m + 1], b.y, vB);  tB = fma2(wgo[2 * m + 1], b.y, tB);
        }
        const u64 aifA = add2(uA, vA), agoA = add2(sA, tA);
        const u64 aifB = add2(uB, vB), agoB = add2(sB, tB);

        float isA, fsA, gsA, osA; unpk2(aifA, isA, fsA); unpk2(agoA, gsA, osA);
        float isB, fsB, gsB, osB; unpk2(aifB, isB, fsB); unpk2(agoB, gsB, osB);

        // batched activations: row A first (its chain is ahead), then row B
        const float eiA = ex2a(isA), efA = ex2a(fsA), egA = ex2a(gsA), eoA = ex2a(osA);
        const float eiB = ex2a(isB), efB = ex2a(fsB), egB = ex2a(gsB), eoB = ex2a(osB);
        const float siA = rcpa(1.0f + eiA), sfA = rcpa(1.0f + efA);
        const float tgA = fmaf(2.0f * TSC, rcpa(1.0f + egA), -TSC);
        const float soA = rcpa(1.0f + eoA);
        const float siB = rcpa(1.0f + eiB), sfB = rcpa(1.0f + efB);
        const float tgB = fmaf(2.0f * TSC, rcpa(1.0f + egB), -TSC);
        const float soB = rcpa(1.0f + eoB);

        cA = fmaf(sfA, cA, siA * tgA);
        cB = fmaf(sfB, cB, siB * tgB);
        hA = soA * tanhU(cA);
        hB = soB * tanhU(cB);

        u64* qA = wb0 + ((p ^ 1) << 6);
        u64* qB = wb1 + ((p ^ 1) << 6);
        qA[32 + lane] = pk2(cA, cA);
        qB[32 + lane] = pk2(cB, cB);
        qA[lane]      = pk2(hA, hA);
        qB[lane]      = pk2(hB, hB);
        p ^= 1;
    };

    // ---- single-row step (future phase) ----
    auto step1 = [&](float x, float& cl, float& hl, u64* base) {
        const ulonglong2* hp = (const ulonglong2*)(base + (p << 6) + sec);
        const u64 xx = pk2(x, x), hh = pk2(hl, hl);
        u64 u = fma2(wh2A, hh, fma2(wxif, xx, bif));
        u64 s = fma2(wh2B, hh, fma2(wxgo, xx, bgo));
        u64 v = 0ull, t = 0ull;
#pragma unroll
        for (int m = 0; m < 10; m++) {
            const ulonglong2 a = hp[m];
            u = fma2(wif[2 * m],     a.x, u);  s = fma2(wgo[2 * m],     a.x, s);
            v = fma2(wif[2 * m + 1], a.y, v);  t = fma2(wgo[2 * m + 1], a.y, t);
        }
        const u64 aif = add2(u, v), ago = add2(s, t);
        float is, fs, gs, os; unpk2(aif, is, fs); unpk2(ago, gs, os);
        const float ei = ex2a(is), ef = ex2a(fs), eg = ex2a(gs), eo = ex2a(os);
        const float si = rcpa(1.0f + ei), sf = rcpa(1.0f + ef);
        const float tg = fmaf(2.0f * TSC, rcpa(1.0f + eg), -TSC);
        const float so = rcpa(1.0f + eo);
        cl = fmaf(sf, cl, si * tg);
        u64* sb = base + ((p ^ 1) << 6);
        sb[32 + lane] = pk2(cl, cl);
        hl = so * tanhU(cl);
        sb[lane] = pk2(hl, hl);
        p ^= 1;
    };

    // ---- butterfly L2 (flush / future phase); c1v is TSC-scaled ----
    auto step_l2 = [&](float c1v, float& c2s, float& h2s) {
        const u64 cc = pk2(c1v, c1v);
        u64 pif = mul2(uifW, cc), pgo = mul2(ugoW, cc);
#pragma unroll
        for (int m = 16; m; m >>= 1) {
            pif = add2(pif, shfl64(pif, m));
            pgo = add2(pgo, shfl64(pgo, m));
        }
        const u64 hh = pk2(h2s, h2s);
        pif = fma2(wh2if, hh, add2(pif, b2if));
        pgo = fma2(wh2go, hh, add2(pgo, b2go));
        float i2, f2, g2, o2; unpk2(pif, i2, f2); unpk2(pgo, g2, o2);
        const float s2i = sigS(i2), s2f = sigS(f2), t2g = tanhU(g2), s2o = sigS(o2);
        c2s = fmaf(s2f, c2s, s2i * t2g);
        h2s = s2o * tanhU(c2s * TSC);
    };

    const float* xr0 = xin + (size_t)b0 * T;
    const float* xr1 = xin + (size_t)(b0 + 1) * T;
    float*       or0 = out + (size_t)b0 * (T + F);
    float*       or1 = out + (size_t)(b0 + 1) * (T + F);

    // ---- peel t = 0: L1 only for both rows; reset lane-20 L2 state ----
    float xn0 = __ldg(xr0 + 1);
    float xn1 = __ldg(xr1 + 1);
    step2(__ldg(xr0), __ldg(xr1));
    if (is20) { cA = 0.0f; hA = 0.0f; cB = 0.0f; hB = 0.0f; }

    // ---- main loop: fused pair, loads-before-stores ----
#pragma unroll 1
    for (int t = 1; t < T; t++) {
        const float x0 = xn0, x1 = xn1;
        if (t + 1 < T) { xn0 = __ldg(xr0 + t + 1); xn1 = __ldg(xr1 + t + 1); }
        step2(x0, x1);
        if (is20) { or0[t - 1] = cA * INV_TSC; or1[t - 1] = cB * INV_TSC; }
    }

    // ---- flush + future, row A ----
    {
        float c2s = __shfl_sync(0xffffffffu, cA, 20) * INV_TSC;
        float h2s = __shfl_sync(0xffffffffu, hA, 20);
        step_l2(cA, c2s, h2s);                 // cA = TSC*c1(T-1) per lane
        if (lane == 0) or0[T - 1] = c2s;
        int psave = p;
#pragma unroll 1
        for (int f = 0; f < F; f++) {
            step1(c2s, cA, hA, wb0);
            step_l2(cA, c2s, h2s);
            if (lane == 0) or0[T + f] = c2s;
        }
        p = psave;
    }
    // ---- flush + future, row B ----
    {
        float c2s = __shfl_sync(0xffffffffu, cB, 20) * INV_TSC;
        float h2s = __shfl_sync(0xffffffffu, hB, 20);
        step_l2(cB, c2s, h2s);
        if (lane == 0) or1[T - 1] = c2s;
#pragma unroll 1
        for (int f = 0; f < F; f++) {
            step1(c2s, cB, hB, wb1);
            step_l2(cB, c2s, h2s);
            if (lane == 0) or1[T + f] = c2s;
        }
    }
}

extern "C" void kernel_launch(void* const* d_in, const int* in_sizes, int n_in,
                              void* d_out, int out_size)
{
    const float* xin  = (const float*)d_in[0];
    const float* Wih1 = (const float*)d_in[1];
    const float* Whh1 = (const float*)d_in[2];
    const float* bih1 = (const float*)d_in[3];
    const float* bhh1 = (const float*)d_in[4];
    const float* Wih2 = (const float*)d_in[5];
    const float* Whh2 = (const float*)d_in[6];
    const float* bih2 = (const float*)d_in[7];
    const float* bhh2 = (const float*)d_in[8];

    const int B = 1024;
    const int T = in_sizes[0] / B;          // 4096
    const int F = out_size / B - T;         // 16

    dim3 grid(B / 8), block(128);           // 128 blocks: 2 rows per warp
    lstm_warp_kernel<<<grid, block>>>(xin, Wih1, Whh1, bih1, bhh1,
                                      Wih2, Whh2, bih2, bhh2,
                                      (float*)d_out, B, T, F);
}

// round 17
// speedup vs baseline: 1.3436x; 1.0902x over previous
#include <cuda_runtime.h>

typedef unsigned long long u64;

// ---------- f32x2 packed helpers (Blackwell sm_103a) ----------
__device__ __forceinline__ u64 pk2(float lo, float hi) {
    u64 r; asm("mov.b64 %0,{%1,%2};" : "=l"(r) : "f"(lo), "f"(hi)); return r;
}
__device__ __forceinline__ void unpk2(u64 v, float& lo, float& hi) {
    asm("mov.b64 {%0,%1},%2;" : "=f"(lo), "=f"(hi) : "l"(v));
}
__device__ __forceinline__ u64 fma2(u64 a, u64 b, u64 c) {
    u64 d; asm("fma.rn.f32x2 %0,%1,%2,%3;" : "=l"(d) : "l"(a), "l"(b), "l"(c)); return d;
}
__device__ __forceinline__ u64 add2(u64 a, u64 b) {
    u64 d; asm("add.rn.f32x2 %0,%1,%2;" : "=l"(d) : "l"(a), "l"(b)); return d;
}
__device__ __forceinline__ u64 mul2(u64 a, u64 b) {
    u64 d; asm("mul.rn.f32x2 %0,%1,%2;" : "=l"(d) : "l"(a), "l"(b)); return d;
}
__device__ __forceinline__ u64 shfl64(u64 v, int m) {
    return __shfl_xor_sync(0xffffffffu, v, m);
}

// ---------- activations (R7 structure — empirically best) ----------
__device__ __forceinline__ float ex2a(float x) {
    float y; asm("ex2.approx.f32 %0,%1;" : "=f"(y) : "f"(x)); return y;
}
__device__ __forceinline__ float rcpa(float x) {
    float y; asm("rcp.approx.f32 %0,%1;" : "=f"(y) : "f"(x)); return y;
}
#define SSC (-1.4426950408889634f)     /* -log2(e)   : sigmoid pre-scale */
#define TSC (-2.8853900817779268f)     /* -2*log2(e) : tanh pre-scale    */
#define INV_TSC (-0.3465735902799726f) /* 1/TSC                          */

__device__ __forceinline__ float sigS(float s)  { return rcpa(1.0f + ex2a(s)); }
__device__ __forceinline__ float tanhU(float s) { return fmaf(2.0f, rcpa(1.0f + ex2a(s)), -1.0f); }

// TWO rows per warp, HALF-STEP STAGGERED: body = actsA -> loadsA -> actsB ->
// dotA -> loadsB -> dotB, so each row's MUFU-heavy act block overlaps the
// OTHER row's fma2 dot (different pipes, no dependence). R16 failed because
// both rows hit the MUFU burst together, exposing 160 cyc of MUFU-rt on the
// chain with the fma pipe idle.
// Per row: lanes 0-19 = layer-1 unit j=lane; lane 20 = all four layer-2 gates
// (c-section dots, weights /TSC, h2 joins at chain pos 2). cloc carries TSC*c.
__global__ void __launch_bounds__(128)
lstm_warp_kernel(const float* __restrict__ xin,
                 const float* __restrict__ Wih1, const float* __restrict__ Whh1,
                 const float* __restrict__ bih1, const float* __restrict__ bhh1,
                 const float* __restrict__ Wih2, const float* __restrict__ Whh2,
                 const float* __restrict__ bih2, const float* __restrict__ bhh2,
                 float* __restrict__ out, int B, int T, int F)
{
    const int w    = threadIdx.x >> 5;
    const int lane = threadIdx.x & 31;
    const int gw   = blockIdx.x * 4 + w;       // global warp id (512 total)
    const int b0   = 2 * gw;                   // rows b0, b0+1

    // [warp][row][ping][0:32)=(h,h) dup, [32:64)=(TSC*c,TSC*c) dup
    __shared__ __align__(16) u64 sbuf[4][2][2][64];

    const bool is20 = (lane == 20);
    const int  sec  = (lane < 20) ? 0 : 32;
    u64* const wb0  = &sbuf[w][0][0][0];
    u64* const wb1  = &sbuf[w][1][0][0];

    // ---- per-lane weights (prescaled, SHARED by both rows); default zero ----
    u64 wif[20], wgo[20];
#pragma unroll
    for (int k = 0; k < 20; k++) { wif[k] = 0ull; wgo[k] = 0ull; }
    u64 wxif = 0ull, wxgo = 0ull, bif = 0ull, bgo = 0ull;
    u64 wh2A = 0ull, wh2B = 0ull;

    if (lane < 20) {
        const int j = lane;
#pragma unroll
        for (int k = 0; k < 20; k++) {
            wif[k] = pk2(SSC * Whh1[j * 20 + k],        SSC * Whh1[(20 + j) * 20 + k]);
            wgo[k] = pk2(TSC * Whh1[(40 + j) * 20 + k], SSC * Whh1[(60 + j) * 20 + k]);
        }
        wxif = pk2(SSC * Wih1[j],      SSC * Wih1[20 + j]);
        wxgo = pk2(TSC * Wih1[40 + j], SSC * Wih1[60 + j]);
        bif  = pk2(SSC * (bih1[j] + bhh1[j]),
                   SSC * (bih1[20 + j] + bhh1[20 + j]));
        bgo  = pk2(TSC * (bih1[40 + j] + bhh1[40 + j]),
                   SSC * (bih1[60 + j] + bhh1[60 + j]));
    } else if (lane == 20) {
#pragma unroll
        for (int k = 0; k < 20; k++) {
            wif[k] = pk2(SSC * INV_TSC * Wih2[k],  SSC * INV_TSC * Wih2[20 + k]);
            wgo[k] = pk2(Wih2[40 + k],             SSC * INV_TSC * Wih2[60 + k]);
        }
        bif  = pk2(SSC * (bih2[0] + bhh2[0]), SSC * (bih2[1] + bhh2[1]));
        bgo  = pk2(TSC * (bih2[2] + bhh2[2]), SSC * (bih2[3] + bhh2[3]));
        wh2A = pk2(SSC * Whh2[0], SSC * Whh2[1]);   // h2 joins at chain pos 2
        wh2B = pk2(TSC * Whh2[2], SSC * Whh2[3]);
    }

    // butterfly-path L2 weights (flush / future phase only); input is TSC*c1
    u64 uifW = 0ull, ugoW = 0ull;
    if (lane < 20) {
        uifW = pk2(SSC * INV_TSC * Wih2[lane],  SSC * INV_TSC * Wih2[20 + lane]);
        ugoW = pk2(Wih2[40 + lane],             SSC * INV_TSC * Wih2[60 + lane]);
    }
    const u64 wh2if = pk2(SSC * Whh2[0], SSC * Whh2[1]);
    const u64 wh2go = pk2(TSC * Whh2[2], SSC * Whh2[3]);
    const u64 b2if  = pk2(SSC * (bih2[0] + bhh2[0]), SSC * (bih2[1] + bhh2[1]));
    const u64 b2go  = pk2(TSC * (bih2[2] + bhh2[2]), SSC * (bih2[3] + bhh2[3]));

    // ---- per-row state ----
    float cA = 0.0f, hA = 0.0f;
    float cB = 0.0f, hB = 0.0f;
    int   p  = 0;
    wb0[lane] = 0ull; wb0[32 + lane] = 0ull;
    wb1[lane] = 0ull; wb1[32 + lane] = 0ull;

    // ---- 20-fma2 dual-gate dot from named loads ----
    auto dotf = [&](float x, float h,
                    ulonglong2 q0, ulonglong2 q1, ulonglong2 q2, ulonglong2 q3,
                    ulonglong2 q4, ulonglong2 q5, ulonglong2 q6, ulonglong2 q7,
                    ulonglong2 q8, ulonglong2 q9, u64& aif, u64& ago) {
        const u64 xx = pk2(x, x), hh = pk2(h, h);
        u64 u = fma2(wh2A, hh, fma2(wxif, xx, bif));
        u64 s = fma2(wh2B, hh, fma2(wxgo, xx, bgo));
        u64 v = mul2(wif[1], q0.y); u64 t2 = mul2(wgo[1], q0.y);
        u = fma2(wif[0],  q0.x, u);   s  = fma2(wgo[0],  q0.x, s);
        v = fma2(wif[3],  q1.y, v);   t2 = fma2(wgo[3],  q1.y, t2);
        u = fma2(wif[2],  q1.x, u);   s  = fma2(wgo[2],  q1.x, s);
        v = fma2(wif[5],  q2.y, v);   t2 = fma2(wgo[5],  q2.y, t2);
        u = fma2(wif[4],  q2.x, u);   s  = fma2(wgo[4],  q2.x, s);
        v = fma2(wif[7],  q3.y, v);   t2 = fma2(wgo[7],  q3.y, t2);
        u = fma2(wif[6],  q3.x, u);   s  = fma2(wgo[6],  q3.x, s);
        v = fma2(wif[9],  q4.y, v);   t2 = fma2(wgo[9],  q4.y, t2);
        u = fma2(wif[8],  q4.x, u);   s  = fma2(wgo[8],  q4.x, s);
        v = fma2(wif[11], q5.y, v);   t2 = fma2(wgo[11], q5.y, t2);
        u = fma2(wif[10], q5.x, u);   s  = fma2(wgo[10], q5.x, s);
        v = fma2(wif[13], q6.y, v);   t2 = fma2(wgo[13], q6.y, t2);
        u = fma2(wif[12], q6.x, u);   s  = fma2(wgo[12], q6.x, s);
        v = fma2(wif[15], q7.y, v);   t2 = fma2(wgo[15], q7.y, t2);
        u = fma2(wif[14], q7.x, u);   s  = fma2(wgo[14], q7.x, s);
        v = fma2(wif[17], q8.y, v);   t2 = fma2(wgo[17], q8.y, t2);
        u = fma2(wif[16], q8.x, u);   s  = fma2(wgo[16], q8.x, s);
        v = fma2(wif[19], q9.y, v);   t2 = fma2(wgo[19], q9.y, t2);
        u = fma2(wif[18], q9.x, u);   s  = fma2(wgo[18], q9.x, s);
        aif = add2(u, v); ago = add2(s, t2);
    };

    // ---- activations + state update + stores (early c-store) ----
    auto actf = [&](u64 aif, u64 ago, float& cl, float& hl, u64* sb) {
        float is, fs, gs, os; unpk2(aif, is, fs); unpk2(ago, gs, os);
        const float ei = ex2a(is), ef = ex2a(fs), eg = ex2a(gs), eo = ex2a(os);
        const float si = rcpa(1.0f + ei), sf = rcpa(1.0f + ef);
        const float tg = fmaf(2.0f * TSC, rcpa(1.0f + eg), -TSC);
        const float so = rcpa(1.0f + eo);
        cl = fmaf(sf, cl, si * tg);
        sb[32 + lane] = pk2(cl, cl);
        hl = so * tanhU(cl);
        sb[lane] = pk2(hl, hl);
    };

    // ---- single-row fused step (future phase) ----
    auto step1 = [&](float x, float& cl, float& hl, u64* base) {
        const ulonglong2* hp = (const ulonglong2*)(base + (p << 6) + sec);
        const ulonglong2 q0 = hp[0], q1 = hp[1], q2 = hp[2], q3 = hp[3], q4 = hp[4];
        const ulonglong2 q5 = hp[5], q6 = hp[6], q7 = hp[7], q8 = hp[8], q9 = hp[9];
        u64 aif, ago;
        dotf(x, hl, q0, q1, q2, q3, q4, q5, q6, q7, q8, q9, aif, ago);
        actf(aif, ago, cl, hl, base + ((p ^ 1) << 6));
        p ^= 1;
    };

    // ---- butterfly L2 (flush / future phase); c1v is TSC-scaled ----
    auto step_l2 = [&](float c1v, float& c2s, float& h2s) {
        const u64 cc = pk2(c1v, c1v);
        u64 pif = mul2(uifW, cc), pgo = mul2(ugoW, cc);
#pragma unroll
        for (int m = 16; m; m >>= 1) {
            pif = add2(pif, shfl64(pif, m));
            pgo = add2(pgo, shfl64(pgo, m));
        }
        const u64 hh = pk2(h2s, h2s);
        pif = fma2(wh2if, hh, add2(pif, b2if));
        pgo = fma2(wh2go, hh, add2(pgo, b2go));
        float i2, f2, g2, o2; unpk2(pif, i2, f2); unpk2(pgo, g2, o2);
        const float s2i = sigS(i2), s2f = sigS(f2), t2g = tanhU(g2), s2o = sigS(o2);
        c2s = fmaf(s2f, c2s, s2i * t2g);
        h2s = s2o * tanhU(c2s * TSC);
    };

    const float* xr0 = xin + (size_t)b0 * T;
    const float* xr1 = xin + (size_t)(b0 + 1) * T;
    float*       or0 = out + (size_t)b0 * (T + F);
    float*       or1 = out + (size_t)(b0 + 1) * (T + F);

    u64 aifA, agoA, aifB, agoB;

    // ---- prologue: dot(0) from zero state, peel body t=0 ----
    {
        const float x0A = __ldg(xr0), x0B = __ldg(xr1);
        const ulonglong2* hpA = (const ulonglong2*)(wb0 + sec);
        const ulonglong2 a0 = hpA[0], a1 = hpA[1], a2 = hpA[2], a3 = hpA[3], a4 = hpA[4];
        const ulonglong2 a5 = hpA[5], a6 = hpA[6], a7 = hpA[7], a8 = hpA[8], a9 = hpA[9];
        dotf(x0A, 0.0f, a0, a1, a2, a3, a4, a5, a6, a7, a8, a9, aifA, agoA);
        const ulonglong2* hpB = (const ulonglong2*)(wb1 + sec);
        const ulonglong2 c0 = hpB[0], c1 = hpB[1], c2 = hpB[2], c3 = hpB[3], c4 = hpB[4];
        const ulonglong2 c5 = hpB[5], c6 = hpB[6], c7 = hpB[7], c8 = hpB[8], c9 = hpB[9];
        dotf(x0B, 0.0f, c0, c1, c2, c3, c4, c5, c6, c7, c8, c9, aifB, agoB);
    }
    float xnA = __ldg(xr0 + 1), xnB = __ldg(xr1 + 1);
    {   // peel body t=0: acts(0) [no output], reset lane-20 L2 state, dot(1)
        u64* sbA = wb0 + 64;     // ping 1
        u64* sbB = wb1 + 64;
        actf(aifA, agoA, cA, hA, sbA);
        actf(aifB, agoB, cB, hB, sbB);
        if (is20) { cA = 0.0f; hA = 0.0f; cB = 0.0f; hB = 0.0f; }
        const ulonglong2* hpA = (const ulonglong2*)(wb0 + 64 + sec);
        const ulonglong2 a0 = hpA[0], a1 = hpA[1], a2 = hpA[2], a3 = hpA[3], a4 = hpA[4];
        const ulonglong2 a5 = hpA[5], a6 = hpA[6], a7 = hpA[7], a8 = hpA[8], a9 = hpA[9];
        dotf(xnA, hA, a0, a1, a2, a3, a4, a5, a6, a7, a8, a9, aifA, agoA);
        const ulonglong2* hpB = (const ulonglong2*)(wb1 + 64 + sec);
        const ulonglong2 c0 = hpB[0], c1 = hpB[1], c2 = hpB[2], c3 = hpB[3], c4 = hpB[4];
        const ulonglong2 c5 = hpB[5], c6 = hpB[6], c7 = hpB[7], c8 = hpB[8], c9 = hpB[9];
        dotf(xnB, hB, c0, c1, c2, c3, c4, c5, c6, c7, c8, c9, aifB, agoB);
        p = 1;
    }
    xnA = __ldg(xr0 + 2); xnB = __ldg(xr1 + 2);

    // ---- main loop: staggered body — acts(t) and dot(t+1), rows半 out of phase
#pragma unroll 1
    for (int t = 1; t < T; t++) {
        const float xA = xnA, xB = xnB;           // x(t+1)
        if (t + 2 < T) { xnA = __ldg(xr0 + t + 2); xnB = __ldg(xr1 + t + 2); }

        const int pn = p ^ 1;
        u64* sbA = wb0 + (pn << 6);
        u64* sbB = wb1 + (pn << 6);

        // acts A(t) + stores
        actf(aifA, agoA, cA, hA, sbA);
        if (is20) or0[t - 1] = cA * INV_TSC;      // c2(t-1), row A

        // loads A (state t) — after A's own STS; gap filled by acts B below
        const ulonglong2* hpA = (const ulonglong2*)(wb0 + (pn << 6) + sec);
        const ulonglong2 a0 = hpA[0], a1 = hpA[1], a2 = hpA[2], a3 = hpA[3], a4 = hpA[4];
        const ulonglong2 a5 = hpA[5], a6 = hpA[6], a7 = hpA[7], a8 = hpA[8], a9 = hpA[9];

        // acts B(t) + stores (MUFU) — overlaps A's load latency and A's dot below
        actf(aifB, agoB, cB, hB, sbB);
        if (is20) or1[t - 1] = cB * INV_TSC;      // c2(t-1), row B

        // dot A(t+1) (fma2) — independent of acts B: interleaves
        dotf(xA, hA, a0, a1, a2, a3, a4, a5, a6, a7, a8, a9, aifA, agoA);

        // loads B (state t) — after B's STS; gap = A's dot above
        const ulonglong2* hpB = (const ulonglong2*)(wb1 + (pn << 6) + sec);
        const ulonglong2 c0 = hpB[0], c1 = hpB[1], c2 = hpB[2], c3 = hpB[3], c4 = hpB[4];
        const ulonglong2 c5 = hpB[5], c6 = hpB[6], c7 = hpB[7], c8 = hpB[8], c9 = hpB[9];

        // dot B(t+1)
        dotf(xB, hB, c0, c1, c2, c3, c4, c5, c6, c7, c8, c9, aifB, agoB);

        p = pn;
    }
    // (gates(T) computed on the last iteration are discarded)

    // ---- flush + future, row A ----
    {
        float c2s = __shfl_sync(0xffffffffu, cA, 20) * INV_TSC;   // c2(T-2)
        float h2s = __shfl_sync(0xffffffffu, hA, 20);             // h2(T-2)
        step_l2(cA, c2s, h2s);                  // cA = TSC*c1(T-1) on lanes<20
        if (lane == 0) or0[T - 1] = c2s;
        int psave = p;
#pragma unroll 1
        for (int f = 0; f < F; f++) {
            step1(c2s, cA, hA, wb0);
            step_l2(cA, c2s, h2s);
            if (lane == 0) or0[T + f] = c2s;
        }
        p = psave;
    }
    // ---- flush + future, row B ----
    {
        float c2s = __shfl_sync(0xffffffffu, cB, 20) * INV_TSC;
        float h2s = __shfl_sync(0xffffffffu, hB, 20);
        step_l2(cB, c2s, h2s);
        if (lane == 0) or1[T - 1] = c2s;
#pragma unroll 1
        for (int f = 0; f < F; f++) {
            step1(c2s, cB, hB, wb1);
            step_l2(cB, c2s, h2s);
            if (lane == 0) or1[T + f] = c2s;
        }
    }
}

extern "C" void kernel_launch(void* const* d_in, const int* in_sizes, int n_in,
                              void* d_out, int out_size)
{
    const float* xin  = (const float*)d_in[0];
    const float* Wih1 = (const float*)d_in[1];
    const float* Whh1 = (const float*)d_in[2];
    const float* bih1 = (const float*)d_in[3];
    const float* bhh1 = (const float*)d_in[4];
    const float* Wih2 = (const float*)d_in[5];
    const float* Whh2 = (const float*)d_in[6];
    const float* bih2 = (const float*)d_in[7];
    const float* bhh2 = (const float*)d_in[8];

    const int B = 1024;
    const int T = in_sizes[0] / B;          // 4096
    const int F = out_size / B - T;         // 16

    dim3 grid(B / 8), block(128);           // 128 blocks: 2 rows per warp
    lstm_warp_kernel<<<grid, block>>>(xin, Wih1, Whh1, bih1, bhh1,
                                      Wih2, Whh2, bih2, bhh2,
                                      (float*)d_out, B, T, F);
}